// round 1
// baseline (speedup 1.0000x reference)
#include <cuda_runtime.h>

// ---------------------------------------------------------------------------
// Fused LeNet-style net: pad(-1) -> conv5x5 s2 (+bias,relu) -> pad(-1) ->
// grouped conv5x5 s2 (+bias,relu) -> FC 192x30 (relu) -> FC 30x10.
// One warp processes one image; all intermediates live in shared memory.
// ---------------------------------------------------------------------------

#define WARPS_PER_BLOCK 4
#define THREADS (WARPS_PER_BLOCK * 32)
#define NBLOCKS 2048

// ---- shared memory layout (floats) ----
// weights (block-shared, loaded once)
#define OFF_W1 0        // 300   (12,1,5,5)
#define OFF_B1 300      // 768   (12,8,8)
#define OFF_W2 1068     // 12*201 = 2412 (stride-201 per oc to kill bank conflicts)
#define OFF_B2 3480     // 192   (12,4,4)
#define OFF_W3 3672     // 5760  (192,30)
#define OFF_B3 9432     // 30
#define OFF_WO 9462     // 300   (30,10)
#define OFF_BO 9762     // 10
#define WBASE  9792     // start of per-warp regions

// per-warp region
#define PW_IN   0               // padded input 20 rows x stride 21 = 420
#define PW_A    420             // padded conv1 act: 12 ch x stride 145 (12x12=144) = 1740
#define PW_B    (420 + 1740)    // conv2 out 192
#define PW_C    (420 + 1740 + 192) // fc1 out 30 (pad 32)
#define PW_SIZE 2384

#define SMEM_FLOATS (WBASE + WARPS_PER_BLOCK * PW_SIZE)   // 19328
#define SMEM_BYTES  (SMEM_FLOATS * 4)                     // 77312

__global__ void __launch_bounds__(THREADS)
modernnet_kernel(const float* __restrict__ x,
                 const float* __restrict__ H1w, const float* __restrict__ H1b,
                 const float* __restrict__ H2w, const float* __restrict__ H2b,
                 const float* __restrict__ H3w, const float* __restrict__ H3b,
                 const float* __restrict__ outw, const float* __restrict__ outb,
                 float* __restrict__ out, int B)
{
    extern __shared__ float smem[];
    const int tid = threadIdx.x;

    // ---- stage all weights/biases into shared ----
    for (int i = tid; i < 300; i += THREADS) smem[OFF_W1 + i] = H1w[i];
    for (int i = tid; i < 768; i += THREADS) smem[OFF_B1 + i] = H1b[i];
    for (int i = tid; i < 2400; i += THREADS) {
        int oc = i / 200, r = i - oc * 200;
        smem[OFF_W2 + oc * 201 + r] = H2w[i];
    }
    for (int i = tid; i < 192;  i += THREADS) smem[OFF_B2 + i] = H2b[i];
    for (int i = tid; i < 5760; i += THREADS) smem[OFF_W3 + i] = H3w[i];
    for (int i = tid; i < 30;   i += THREADS) smem[OFF_B3 + i] = H3b[i];
    for (int i = tid; i < 300;  i += THREADS) smem[OFF_WO + i] = outw[i];
    for (int i = tid; i < 10;   i += THREADS) smem[OFF_BO + i] = outb[i];

    const int warp = tid >> 5;
    const int lane = tid & 31;
    float* const pw  = smem + WBASE + warp * PW_SIZE;
    float* const sIn = pw + PW_IN;   // padded input  [20][21], interior at (2,2)
    float* const sA  = pw + PW_A;    // padded act1   [12][12x12 pad->145], interior rows/cols 2..9
    float* const sB  = pw + PW_B;    // conv2 out [192]
    float* const sC  = pw + PW_C;    // fc1 out [30]

    // fill pad buffers with -1 ONCE; interiors are overwritten every image,
    // borders stay -1 forever (matches jnp.pad(constant_values=-1)).
    for (int i = lane; i < 420;  i += 32) sIn[i] = -1.0f;
    for (int i = lane; i < 1740; i += 32) sA[i]  = -1.0f;

    __syncthreads();   // weights + pad-fills visible

    const int gwarp  = blockIdx.x * WARPS_PER_BLOCK + warp;
    const int nwarps = gridDim.x * WARPS_PER_BLOCK;

    for (int img = gwarp; img < B; img += nwarps) {
        // ---- load input image (16x16) into padded shared, coalesced float4 ----
        const float4* xin = (const float4*)(x + (size_t)img * 256);
        #pragma unroll
        for (int j = 0; j < 2; j++) {
            int f4  = j * 32 + lane;      // 0..63
            float4 v = xin[f4];
            int row = f4 >> 2;            // 4 float4 per 16-col row
            int col = (f4 & 3) * 4;
            float* dst = sIn + (row + 2) * 21 + (col + 2);
            dst[0] = v.x; dst[1] = v.y; dst[2] = v.z; dst[3] = v.w;
        }
        __syncwarp();

        // ---- conv1: 12 ch x 8x8 out, 5x5 s2 over padded 20x20 ----
        // task = (channel, output-row); 96 tasks, 3 per lane.
        #pragma unroll
        for (int t = 0; t < 3; t++) {
            int task = lane + 32 * t;
            int c  = task >> 3;
            int oy = task & 7;
            const float* wp = smem + OFF_W1 + c * 25;
            float w[25];
            #pragma unroll
            for (int i = 0; i < 25; i++) w[i] = wp[i];
            float acc[8];
            #pragma unroll
            for (int i = 0; i < 8; i++) acc[i] = 0.0f;
            #pragma unroll
            for (int ky = 0; ky < 5; ky++) {
                const float* ip = sIn + (2 * oy + ky) * 21;
                float in[19];
                #pragma unroll
                for (int i = 0; i < 19; i++) in[i] = ip[i];
                #pragma unroll
                for (int kx = 0; kx < 5; kx++) {
                    float wv = w[ky * 5 + kx];
                    #pragma unroll
                    for (int ox = 0; ox < 8; ox++)
                        acc[ox] += in[2 * ox + kx] * wv;
                }
            }
            const float* bp = smem + OFF_B1 + c * 64 + oy * 8;
            float* ap = sA + c * 145 + (oy + 2) * 12 + 2;
            #pragma unroll
            for (int ox = 0; ox < 8; ox++)
                ap[ox] = fmaxf(acc[ox] + bp[ox], 0.0f);
        }
        __syncwarp();

        // ---- conv2: grouped, 12 oc x 4x4 out, each oc reads 8 of 12 in-ch ----
        // task = (oc, output-row); 48 tasks.
        #pragma unroll
        for (int t = 0; t < 2; t++) {
            int task = lane + 32 * t;
            if (task < 48) {
                int oc  = task >> 2;
                int oy  = task & 3;
                int grp = oc >> 2;
                float acc[4] = {0.0f, 0.0f, 0.0f, 0.0f};
                #pragma unroll 1
                for (int g = 0; g < 8; g++) {
                    // grp0: ic=g (x[0:8]); grp1: ic=g+4 (x[4:12]);
                    // grp2: ic = g<4 ? g : g+4 (x[0:4]++x[8:12])
                    int ic = g + ((grp == 1) ? 4 : ((grp == 2 && g >= 4) ? 4 : 0));
                    const float* wp = smem + OFF_W2 + oc * 201 + g * 25;
                    float w[25];
                    #pragma unroll
                    for (int i = 0; i < 25; i++) w[i] = wp[i];
                    const float* icb = sA + ic * 145;
                    #pragma unroll
                    for (int ky = 0; ky < 5; ky++) {
                        const float* ip = icb + (2 * oy + ky) * 12;
                        float in[11];
                        #pragma unroll
                        for (int i = 0; i < 11; i++) in[i] = ip[i];
                        #pragma unroll
                        for (int kx = 0; kx < 5; kx++) {
                            float wv = w[ky * 5 + kx];
                            #pragma unroll
                            for (int ox = 0; ox < 4; ox++)
                                acc[ox] += in[2 * ox + kx] * wv;
                        }
                    }
                }
                const float* bp = smem + OFF_B2 + oc * 16 + oy * 4;
                float* op = sB + oc * 16 + oy * 4;
                #pragma unroll
                for (int ox = 0; ox < 4; ox++)
                    op[ox] = fmaxf(acc[ox] + bp[ox], 0.0f);
            }
        }
        __syncwarp();

        // ---- FC1: [192] -> [30], relu ----
        if (lane < 30) {
            float acc = smem[OFF_B3 + lane];
            const float* wp = smem + OFF_W3 + lane;
            #pragma unroll 8
            for (int k = 0; k < 192; k++)
                acc += sB[k] * wp[k * 30];
            sC[lane] = fmaxf(acc, 0.0f);
        }
        __syncwarp();

        // ---- FC2: [30] -> [10] ----
        if (lane < 10) {
            float acc = smem[OFF_BO + lane];
            const float* wp = smem + OFF_WO + lane;
            #pragma unroll
            for (int j = 0; j < 30; j++)
                acc += sC[j] * wp[j * 10];
            out[(size_t)img * 10 + lane] = acc;
        }
        __syncwarp();
    }
}

extern "C" void kernel_launch(void* const* d_in, const int* in_sizes, int n_in,
                              void* d_out, int out_size)
{
    const float* x    = (const float*)d_in[0];
    const float* H1w  = (const float*)d_in[1];
    const float* H1b  = (const float*)d_in[2];
    const float* H2w  = (const float*)d_in[3];
    const float* H2b  = (const float*)d_in[4];
    const float* H3w  = (const float*)d_in[5];
    const float* H3b  = (const float*)d_in[6];
    const float* outw = (const float*)d_in[7];
    const float* outb = (const float*)d_in[8];
    float* out = (float*)d_out;

    int B = in_sizes[0] / 256;

    static bool attr_set = false;
    if (!attr_set) {
        cudaFuncSetAttribute(modernnet_kernel,
                             cudaFuncAttributeMaxDynamicSharedMemorySize,
                             SMEM_BYTES);
        attr_set = true;
    }

    modernnet_kernel<<<NBLOCKS, THREADS, SMEM_BYTES>>>(
        x, H1w, H1b, H2w, H2b, H3w, H3b, outw, outb, out, B);
}

// round 2
// speedup vs baseline: 1.2412x; 1.2412x over previous
#include <cuda_runtime.h>

// ---------------------------------------------------------------------------
// Fused LeNet-style net, vectorized-LDS edition.
// pad(-1) -> conv5x5 s2 (+bias,relu) -> pad(-1) -> grouped conv5x5 s2
// (+bias,relu) -> FC 192x30 (relu) -> FC 30x10.
// One warp per image; intermediates in shared; all hot shared traffic is
// LDS.128 with conflict-engineered strides.
// ---------------------------------------------------------------------------

#define WARPS_PER_BLOCK 6
#define THREADS (WARPS_PER_BLOCK * 32)
#define NBLOCKS 2048

// ---- shared layout (float indices) ----
#define OFF_W1 0          // 12 x 28  = 336   (25 used per ch)
#define OFF_B1 336        // 12 x 64  = 768
#define OFF_W2 1104       // 12 x 228 (8 x 28 within oc) = 2736
#define OFF_B2 3840       // 192
#define OFF_W3 4032       // 192 x 30 = 5760
#define OFF_B3 9792       // 30
#define OFF_WO 9824       // 300
#define OFF_BO 10124      // 10
#define WBASE  10136      // per-warp regions (16B aligned: 10136%4==0)

// per-warp region (floats)
#define PW_INE  0                 // even padded rows: 10 x 20 = 200
#define PW_INO  200               // odd  padded rows: 10 x 20 = 200
#define PW_A    400               // act1: 12 slots x 148 (rows stride 12) = 1776
#define PW_B    (400 + 1776)      // conv2 out: 192
#define PW_C    (400 + 1776 + 192)// fc1 out: 32
#define PW_SIZE 2400

#define SMEM_FLOATS (WBASE + WARPS_PER_BLOCK * PW_SIZE)  // 24536
#define SMEM_BYTES  (SMEM_FLOATS * 4)                    // 98144

__device__ __forceinline__ int slot_of(int c) { return (c & 3) * 3 + (c >> 2); }

__global__ void __launch_bounds__(THREADS, 2)
modernnet_kernel(const float* __restrict__ x,
                 const float* __restrict__ H1w, const float* __restrict__ H1b,
                 const float* __restrict__ H2w, const float* __restrict__ H2b,
                 const float* __restrict__ H3w, const float* __restrict__ H3b,
                 const float* __restrict__ outw, const float* __restrict__ outb,
                 float* __restrict__ out, int B)
{
    extern __shared__ float smem[];
    const int tid = threadIdx.x;

    // ---- stage weights/biases into shared (padded layouts) ----
    for (int i = tid; i < 300; i += THREADS) {
        int c = i / 25, wi = i - c * 25;
        smem[OFF_W1 + c * 28 + wi] = H1w[i];
    }
    for (int i = tid; i < 768; i += THREADS) smem[OFF_B1 + i] = H1b[i];
    for (int i = tid; i < 2400; i += THREADS) {
        int oc = i / 200, r = i - oc * 200;
        int g = r / 25, wi = r - g * 25;
        smem[OFF_W2 + oc * 228 + g * 28 + wi] = H2w[i];
    }
    for (int i = tid; i < 192;  i += THREADS) smem[OFF_B2 + i] = H2b[i];
    for (int i = tid; i < 5760; i += THREADS) smem[OFF_W3 + i] = H3w[i];
    for (int i = tid; i < 30;   i += THREADS) smem[OFF_B3 + i] = H3b[i];
    for (int i = tid; i < 300;  i += THREADS) smem[OFF_WO + i] = outw[i];
    for (int i = tid; i < 10;   i += THREADS) smem[OFF_BO + i] = outb[i];

    const int warp = tid >> 5;
    const int lane = tid & 31;
    float* const pw   = smem + WBASE + warp * PW_SIZE;
    float* const sInE = pw + PW_INE;  // padded even rows [10][20], interior cols 2..17
    float* const sInO = pw + PW_INO;  // padded odd rows
    float* const sA   = pw + PW_A;    // act1: slot*148 + row*12, interior rows/cols 2..9
    float* const sB   = pw + PW_B;
    float* const sC   = pw + PW_C;

    // pad-fill once; interiors overwritten per image, borders stay -1
    for (int i = lane; i < 400;  i += 32) sInE[i] = -1.0f;   // covers sInE+sInO
    for (int i = lane; i < 1776; i += 32) sA[i]   = -1.0f;

    __syncthreads();

    const int gwarp  = blockIdx.x * WARPS_PER_BLOCK + warp;
    const int nwarps = gridDim.x * WARPS_PER_BLOCK;

    for (int img = gwarp; img < B; img += nwarps) {
        // ---- load input (16x16) into even/odd padded row buffers ----
        const float4* xin = (const float4*)(x + (size_t)img * 256);
        #pragma unroll
        for (int j = 0; j < 2; j++) {
            int f4 = j * 32 + lane;          // 0..63
            float4 v = xin[f4];
            int ir = f4 >> 2;                // image row 0..15
            int c4 = f4 & 3;
            int pr = (ir + 2) >> 1;          // packed row in parity buffer
            float* dst = ((ir & 1) ? sInO : sInE) + pr * 20 + 2 + c4 * 4;
            *(float2*)dst       = make_float2(v.x, v.y);
            *(float2*)(dst + 2) = make_float2(v.z, v.w);
        }
        __syncwarp();

        // ---- conv1: tasks (c, oy); 96 tasks over 3 iterations ----
        #pragma unroll
        for (int t = 0; t < 3; t++) {
            int task = lane + 32 * t;
            int c  = task >> 3;
            int oy = task & 7;
            float w[28];
            {
                const float4* wp = (const float4*)(smem + OFF_W1 + c * 28);
                #pragma unroll
                for (int v = 0; v < 7; v++) *(float4*)(w + 4 * v) = wp[v];
            }
            float acc[8];
            {
                const float4* bp = (const float4*)(smem + OFF_B1 + c * 64 + oy * 8);
                float4 b0 = bp[0], b1 = bp[1];
                acc[0]=b0.x; acc[1]=b0.y; acc[2]=b0.z; acc[3]=b0.w;
                acc[4]=b1.x; acc[5]=b1.y; acc[6]=b1.z; acc[7]=b1.w;
            }
            #pragma unroll
            for (int ky = 0; ky < 5; ky++) {
                const float* rp = ((ky & 1) ? sInO : sInE) + (oy + (ky >> 1)) * 20;
                float in[20];
                #pragma unroll
                for (int v = 0; v < 5; v++)
                    *(float4*)(in + 4 * v) = ((const float4*)rp)[v];
                #pragma unroll
                for (int kx = 0; kx < 5; kx++) {
                    float wv = w[ky * 5 + kx];
                    #pragma unroll
                    for (int ox = 0; ox < 8; ox++)
                        acc[ox] += in[2 * ox + kx] * wv;
                }
            }
            float* ap = sA + slot_of(c) * 148 + (oy + 2) * 12 + 2;
            #pragma unroll
            for (int j = 0; j < 4; j++)
                *(float2*)(ap + 2 * j) =
                    make_float2(fmaxf(acc[2*j], 0.0f), fmaxf(acc[2*j+1], 0.0f));
        }
        __syncwarp();

        // ---- conv2: tasks (oc, oy); 48 tasks over 2 iterations ----
        #pragma unroll
        for (int t = 0; t < 2; t++) {
            int task = lane + 32 * t;
            if (task < 48) {
                int oc  = task >> 2;
                int oy  = task & 3;
                int grp = oc >> 2;
                float4 bv = *(const float4*)(smem + OFF_B2 + oc * 16 + oy * 4);
                float acc[4] = {bv.x, bv.y, bv.z, bv.w};
                #pragma unroll 1
                for (int g = 0; g < 8; g++) {
                    int ic = g + ((grp == 1) ? 4 : ((grp == 2 && g >= 4) ? 4 : 0));
                    int sl = (ic & 3) * 3 + (ic >> 2);
                    float w[28];
                    {
                        const float4* wp =
                            (const float4*)(smem + OFF_W2 + oc * 228 + g * 28);
                        #pragma unroll
                        for (int v = 0; v < 7; v++) *(float4*)(w + 4 * v) = wp[v];
                    }
                    const float* icb = sA + sl * 148;
                    #pragma unroll
                    for (int ky = 0; ky < 5; ky++) {
                        const float* rp = icb + (2 * oy + ky) * 12;
                        float in[12];
                        #pragma unroll
                        for (int v = 0; v < 3; v++)
                            *(float4*)(in + 4 * v) = ((const float4*)rp)[v];
                        #pragma unroll
                        for (int kx = 0; kx < 5; kx++) {
                            float wv = w[ky * 5 + kx];
                            #pragma unroll
                            for (int ox = 0; ox < 4; ox++)
                                acc[ox] += in[2 * ox + kx] * wv;
                        }
                    }
                }
                *(float4*)(sB + oc * 16 + oy * 4) =
                    make_float4(fmaxf(acc[0], 0.0f), fmaxf(acc[1], 0.0f),
                                fmaxf(acc[2], 0.0f), fmaxf(acc[3], 0.0f));
            }
        }
        __syncwarp();

        // ---- FC1: [192] -> [30], relu ----
        if (lane < 30) {
            float acc = smem[OFF_B3 + lane];
            const float4* b4 = (const float4*)sB;
            const float* wp = smem + OFF_W3 + lane;
            #pragma unroll 4
            for (int k4 = 0; k4 < 48; k4++) {
                float4 v = b4[k4];
                int k = 4 * k4;
                acc += v.x * wp[(k    ) * 30];
                acc += v.y * wp[(k + 1) * 30];
                acc += v.z * wp[(k + 2) * 30];
                acc += v.w * wp[(k + 3) * 30];
            }
            sC[lane] = fmaxf(acc, 0.0f);
        }
        __syncwarp();

        // ---- FC2: [30] -> [10] ----
        if (lane < 10) {
            float acc = smem[OFF_BO + lane];
            const float* wp = smem + OFF_WO + lane;
            #pragma unroll
            for (int j = 0; j < 30; j++)
                acc += sC[j] * wp[j * 10];
            out[(size_t)img * 10 + lane] = acc;
        }
        __syncwarp();
    }
}

extern "C" void kernel_launch(void* const* d_in, const int* in_sizes, int n_in,
                              void* d_out, int out_size)
{
    const float* x    = (const float*)d_in[0];
    const float* H1w  = (const float*)d_in[1];
    const float* H1b  = (const float*)d_in[2];
    const float* H2w  = (const float*)d_in[3];
    const float* H2b  = (const float*)d_in[4];
    const float* H3w  = (const float*)d_in[5];
    const float* H3b  = (const float*)d_in[6];
    const float* outw = (const float*)d_in[7];
    const float* outb = (const float*)d_in[8];
    float* out = (float*)d_out;

    int B = in_sizes[0] / 256;

    static bool attr_set = false;
    if (!attr_set) {
        cudaFuncSetAttribute(modernnet_kernel,
                             cudaFuncAttributeMaxDynamicSharedMemorySize,
                             SMEM_BYTES);
        attr_set = true;
    }

    modernnet_kernel<<<NBLOCKS, THREADS, SMEM_BYTES>>>(
        x, H1w, H1b, H2w, H2b, H3w, H3b, outw, outb, out, B);
}

// round 4
// speedup vs baseline: 1.9893x; 1.6027x over previous
#include <cuda_runtime.h>

// ---------------------------------------------------------------------------
// Image-per-lane restructure (retry after infra failure). 3 kernels:
//  1) transpose  : x[B][256] -> g_xt[256][B]
//  2) conv1      : per-lane conv (pad -1, 5x5 s2, bias, relu) -> g_a1[768][B]
//  3) conv2 + FC : per-lane grouped conv + FC1(relu) + FC2 -> out
// All activations live in registers (one image per lane); weights are
// broadcast from shared; all global traffic is coalesced via [pos][img].
// ---------------------------------------------------------------------------

#define MAXB 131072

__device__ float g_xt[256 * MAXB];   // transposed input
__device__ float g_a1[768 * MAXB];   // transposed conv1 activations (unpadded)

// ---------------- transpose ----------------
__global__ void __launch_bounds__(256)
transpose_kernel(const float* __restrict__ x, int B)
{
    __shared__ float t[32][33];
    int img0 = blockIdx.x * 32;
    int pos0 = blockIdx.y * 32;
    int tx = threadIdx.x & 31;
    int ty = threadIdx.x >> 5;     // 0..7
    #pragma unroll
    for (int j = 0; j < 32; j += 8)
        t[ty + j][tx] = x[(size_t)(img0 + ty + j) * 256 + pos0 + tx];
    __syncthreads();
    #pragma unroll
    for (int j = 0; j < 32; j += 8)
        g_xt[(size_t)(pos0 + ty + j) * B + img0 + tx] = t[tx][ty + j];
}

// ---------------- conv1 ----------------
// padded row load: padded row pr (0..19) of 20 cols; real rows are pr 2..17.
#define K1_ROW(d, pr) do {                                                   \
    (d)[0] = -1.f; (d)[1] = -1.f; (d)[18] = -1.f; (d)[19] = -1.f;            \
    if ((pr) >= 2 && (pr) <= 17) {                                           \
        const float* _p = xi + (size_t)(((pr) - 2) * 16) * B;                \
        _Pragma("unroll")                                                    \
        for (int _i = 0; _i < 16; _i++) (d)[2 + _i] = _p[(size_t)_i * B];    \
    } else {                                                                 \
        _Pragma("unroll")                                                    \
        for (int _i = 0; _i < 16; _i++) (d)[2 + _i] = -1.f;                  \
    } } while (0)

#define K1_THREADS 128

__global__ void __launch_bounds__(K1_THREADS)
conv1_kernel(const float* __restrict__ H1w, const float* __restrict__ H1b, int B)
{
    __shared__ float sw[12 * 28];
    __shared__ float sb[768];
    int tid = threadIdx.x;
    for (int i = tid; i < 300; i += K1_THREADS) {
        int c = i / 25, k = i - c * 25;
        sw[c * 28 + k] = H1w[i];
    }
    for (int i = tid; i < 768; i += K1_THREADS) sb[i] = H1b[i];
    __syncthreads();

    int lane = tid & 31;
    int gw = blockIdx.x * (K1_THREADS / 32) + (tid >> 5);
    int nw = gridDim.x * (K1_THREADS / 32);
    int nblk = B >> 5;

    for (int blk = gw; blk < nblk; blk += nw) {
        int img = (blk << 5) + lane;
        const float* xi = g_xt + img;
        float* ao = g_a1 + img;

        #pragma unroll 1
        for (int oy = 0; oy < 8; ++oy) {
            float rbuf[5][20];
            #pragma unroll
            for (int ky = 0; ky < 5; ky++) {
                int pr = 2 * oy + ky;
                K1_ROW(rbuf[ky], pr);
            }
            #pragma unroll 1
            for (int c = 0; c < 12; c++) {
                float acc[8];
                {
                    const float4* b4 = (const float4*)(sb + c * 64 + oy * 8);
                    float4 b0 = b4[0], b1 = b4[1];
                    acc[0]=b0.x; acc[1]=b0.y; acc[2]=b0.z; acc[3]=b0.w;
                    acc[4]=b1.x; acc[5]=b1.y; acc[6]=b1.z; acc[7]=b1.w;
                }
                #pragma unroll
                for (int ky = 0; ky < 5; ky++) {
                    const float* r = rbuf[ky];
                    #pragma unroll
                    for (int kx = 0; kx < 5; kx++) {
                        float wv = sw[c * 28 + ky * 5 + kx];
                        #pragma unroll
                        for (int ox = 0; ox < 8; ox++)
                            acc[ox] += r[2 * ox + kx] * wv;
                    }
                }
                #pragma unroll
                for (int ox = 0; ox < 8; ox++)
                    ao[(size_t)(c * 64 + oy * 8 + ox) * B] = fmaxf(acc[ox], 0.f);
            }
        }
    }
}

// ---------------- conv2 + FC ----------------
// padded act1 row: 12 cols; real rows/cols are 2..9 of the 12x12 pad.
#define K2_ROW(d, pr) do {                                                   \
    (d)[0] = -1.f; (d)[1] = -1.f; (d)[10] = -1.f; (d)[11] = -1.f;            \
    if ((pr) >= 2 && (pr) <= 9) {                                            \
        const float* _p = ci + (size_t)(((pr) - 2) * 8) * B;                 \
        _Pragma("unroll")                                                    \
        for (int _i = 0; _i < 8; _i++) (d)[2 + _i] = _p[(size_t)_i * B];     \
    } else {                                                                 \
        _Pragma("unroll")                                                    \
        for (int _i = 0; _i < 8; _i++) (d)[2 + _i] = -1.f;                   \
    } } while (0)

#define K2_THREADS 128
// dynamic smem layout (float indices)
#define S_W2  0                     // 2400  H2w natural [oc][ic8][25]
#define S_B2  2400                  // 192
#define S_W3  2592                  // 192 x 32 (row stride 32) = 6144
#define S_B3  8736                  // 32
#define S_WO  8768                  // 30 x 12 padded = 360
#define S_BO  9128                  // 12 (padded)
#define S_STG 9152                  // 4 warps x 2048 (64 x 32 lanes)
#define S_TOT (9152 + 4 * 2048)     // 17344 floats
#define S_BYTES (S_TOT * 4)         // 69376 bytes

__global__ void __launch_bounds__(K2_THREADS)
conv2fc_kernel(const float* __restrict__ H2w, const float* __restrict__ H2b,
               const float* __restrict__ H3w, const float* __restrict__ H3b,
               const float* __restrict__ outw, const float* __restrict__ outb,
               float* __restrict__ out, int B)
{
    extern __shared__ float sm[];
    int tid = threadIdx.x;
    for (int i = tid; i < 2400; i += K2_THREADS) sm[S_W2 + i] = H2w[i];
    for (int i = tid; i < 192;  i += K2_THREADS) sm[S_B2 + i] = H2b[i];
    for (int i = tid; i < 5760; i += K2_THREADS) {
        int k = i / 30, j = i - k * 30;
        sm[S_W3 + k * 32 + j] = H3w[i];
    }
    for (int i = tid; i < 30;  i += K2_THREADS) sm[S_B3 + i] = H3b[i];
    for (int i = tid; i < 360; i += K2_THREADS) {
        int k = i / 12, j = i - k * 12;
        sm[S_WO + i] = (j < 10) ? outw[k * 10 + j] : 0.f;
    }
    for (int i = tid; i < 12; i += K2_THREADS)
        sm[S_BO + i] = (i < 10) ? outb[i] : 0.f;
    __syncthreads();

    int lane = tid & 31;
    int warp = tid >> 5;
    float* stg = sm + S_STG + warp * 2048;

    int gw = blockIdx.x * (K2_THREADS / 32) + warp;
    int nw = gridDim.x * (K2_THREADS / 32);
    int nblk = B >> 5;

    for (int blk = gw; blk < nblk; blk += nw) {
        int img = (blk << 5) + lane;
        const float* ai = g_a1 + img;

        float fc1[30];
        #pragma unroll
        for (int j = 0; j < 30; j++) fc1[j] = sm[S_B3 + j];

        #pragma unroll 1
        for (int grp = 0; grp < 3; grp++) {
            float acc[64];
            #pragma unroll
            for (int t = 0; t < 64; t++) acc[t] = sm[S_B2 + grp * 64 + t];

            #pragma unroll 1
            for (int icl = 0; icl < 8; icl++) {
                int c = icl + ((grp == 1) ? 4 : ((grp == 2 && icl >= 4) ? 4 : 0));
                const float* ci = ai + (size_t)(c * 64) * B;
                float ar[7][12];

                // ---- half 0: padded rows 0..6, output rows oy = 0,1 ----
                #pragma unroll
                for (int rr = 0; rr < 7; rr++) { K2_ROW(ar[rr], rr); }
                #pragma unroll
                for (int o = 0; o < 4; o++) {
                    const float* wp = sm + S_W2 + ((grp * 4 + o) * 8 + icl) * 25;
                    float w[25];
                    #pragma unroll
                    for (int k = 0; k < 25; k++) w[k] = wp[k];
                    #pragma unroll
                    for (int oy = 0; oy < 2; oy++) {
                        #pragma unroll
                        for (int ky = 0; ky < 5; ky++) {
                            const float* r = ar[2 * oy + ky];
                            #pragma unroll
                            for (int kx = 0; kx < 5; kx++) {
                                float wv = w[ky * 5 + kx];
                                #pragma unroll
                                for (int ox = 0; ox < 4; ox++)
                                    acc[o * 16 + oy * 4 + ox] += r[2 * ox + kx] * wv;
                            }
                        }
                    }
                }

                // ---- half 1: padded rows 4..10, output rows oy = 2,3 ----
                #pragma unroll
                for (int rr = 0; rr < 7; rr++) { K2_ROW(ar[rr], rr + 4); }
                #pragma unroll
                for (int o = 0; o < 4; o++) {
                    const float* wp = sm + S_W2 + ((grp * 4 + o) * 8 + icl) * 25;
                    float w[25];
                    #pragma unroll
                    for (int k = 0; k < 25; k++) w[k] = wp[k];
                    #pragma unroll
                    for (int oy = 0; oy < 2; oy++) {
                        #pragma unroll
                        for (int ky = 0; ky < 5; ky++) {
                            const float* r = ar[2 * oy + ky];
                            #pragma unroll
                            for (int kx = 0; kx < 5; kx++) {
                                float wv = w[ky * 5 + kx];
                                #pragma unroll
                                for (int ox = 0; ox < 4; ox++)
                                    acc[o * 16 + (oy + 2) * 4 + ox] += r[2 * ox + kx] * wv;
                            }
                        }
                    }
                }
            }

            // relu + stage to per-lane smem column (runtime-indexable)
            #pragma unroll
            for (int t = 0; t < 64; t++)
                stg[t * 32 + lane] = fmaxf(acc[t], 0.f);

            // FC1 partial accumulation for this group's 64 inputs
            const float* w3p = sm + S_W3 + grp * 64 * 32;
            #pragma unroll 1
            for (int k = 0; k < 64; k++) {
                float v = stg[k * 32 + lane];
                const float4* wr = (const float4*)(w3p + k * 32);
                float4 a0 = wr[0], a1 = wr[1], a2 = wr[2], a3 = wr[3];
                float4 a4 = wr[4], a5 = wr[5], a6 = wr[6];
                float2 a7 = *(const float2*)(w3p + k * 32 + 28);
                fc1[0]+=v*a0.x;  fc1[1]+=v*a0.y;  fc1[2]+=v*a0.z;  fc1[3]+=v*a0.w;
                fc1[4]+=v*a1.x;  fc1[5]+=v*a1.y;  fc1[6]+=v*a1.z;  fc1[7]+=v*a1.w;
                fc1[8]+=v*a2.x;  fc1[9]+=v*a2.y;  fc1[10]+=v*a2.z; fc1[11]+=v*a2.w;
                fc1[12]+=v*a3.x; fc1[13]+=v*a3.y; fc1[14]+=v*a3.z; fc1[15]+=v*a3.w;
                fc1[16]+=v*a4.x; fc1[17]+=v*a4.y; fc1[18]+=v*a4.z; fc1[19]+=v*a4.w;
                fc1[20]+=v*a5.x; fc1[21]+=v*a5.y; fc1[22]+=v*a5.z; fc1[23]+=v*a5.w;
                fc1[24]+=v*a6.x; fc1[25]+=v*a6.y; fc1[26]+=v*a6.z; fc1[27]+=v*a6.w;
                fc1[28]+=v*a7.x; fc1[29]+=v*a7.y;
            }
        }

        // ---- FC2 via stage (relu on fc1 first) ----
        #pragma unroll
        for (int j = 0; j < 30; j++)
            stg[j * 32 + lane] = fmaxf(fc1[j], 0.f);

        float res[12];
        #pragma unroll
        for (int j = 0; j < 12; j++) res[j] = sm[S_BO + j];

        #pragma unroll 1
        for (int k = 0; k < 30; k++) {
            float v = stg[k * 32 + lane];
            const float4* wr = (const float4*)(sm + S_WO + k * 12);
            float4 b0 = wr[0], b1 = wr[1], b2 = wr[2];
            res[0]+=v*b0.x;  res[1]+=v*b0.y;  res[2]+=v*b0.z;  res[3]+=v*b0.w;
            res[4]+=v*b1.x;  res[5]+=v*b1.y;  res[6]+=v*b1.z;  res[7]+=v*b1.w;
            res[8]+=v*b2.x;  res[9]+=v*b2.y;  res[10]+=v*b2.z; res[11]+=v*b2.w;
        }

        float* op = out + (size_t)img * 10;
        #pragma unroll
        for (int j = 0; j < 10; j++) op[j] = res[j];
    }
}

// ---------------- launch ----------------
extern "C" void kernel_launch(void* const* d_in, const int* in_sizes, int n_in,
                              void* d_out, int out_size)
{
    const float* x    = (const float*)d_in[0];
    const float* H1w  = (const float*)d_in[1];
    const float* H1b  = (const float*)d_in[2];
    const float* H2w  = (const float*)d_in[3];
    const float* H2b  = (const float*)d_in[4];
    const float* H3w  = (const float*)d_in[5];
    const float* H3b  = (const float*)d_in[6];
    const float* outw = (const float*)d_in[7];
    const float* outb = (const float*)d_in[8];
    float* out = (float*)d_out;

    int B = in_sizes[0] / 256;

    static bool attr_set = false;
    if (!attr_set) {
        cudaFuncSetAttribute(conv2fc_kernel,
                             cudaFuncAttributeMaxDynamicSharedMemorySize,
                             S_BYTES);
        attr_set = true;
    }

    dim3 tgrid(B / 32, 8);
    transpose_kernel<<<tgrid, 256>>>(x, B);

    int nblk = B / 32;                       // 32-image warp blocks
    int g1 = (nblk + (K1_THREADS/32) - 1) / (K1_THREADS/32);
    if (g1 > 1184) g1 = 1184;                // 8 waves of 148 SMs
    conv1_kernel<<<g1, K1_THREADS>>>(H1w, H1b, B);

    int g2 = (nblk + (K2_THREADS/32) - 1) / (K2_THREADS/32);
    if (g2 > 1184) g2 = 1184;
    conv2fc_kernel<<<g2, K2_THREADS, S_BYTES>>>(H2w, H2b, H3w, H3b,
                                                outw, outb, out, B);
}